// round 1
// baseline (speedup 1.0000x reference)
#include <cuda_runtime.h>
#include <math.h>

#define BB 2
#define TT 2048
#define DD 1024
#define HH 16
#define HD 64
#define MM (BB*TT)

// Scratch (device globals: no allocations allowed)
__device__ float g_qk [(size_t)MM * 2 * DD];  // [B,T,2D]  q|k projections
__device__ float g_k2 [(size_t)MM * DD];      // [B,T,D]
__device__ float g_yar[(size_t)MM * DD];      // merged [B,T,D]
__device__ float g_yma[(size_t)MM * DD];      // merged [B,T,D]

// ---------------------------------------------------------------------------
// C[m][n] = (A[m][k] (+ A2[m][k])) * W[n][k] + bscale*bias[n]
// Tiles 64x64, BK=32, 256 threads, 4x4 micro-tile per thread.
// ---------------------------------------------------------------------------
__global__ void __launch_bounds__(256) gemm_atb_kernel(
    const float* __restrict__ A, const float* __restrict__ A2,
    const float* __restrict__ W, const float* __restrict__ bias,
    float bscale, float* __restrict__ C, int N, int K)
{
    __shared__ float As[32][64];   // [k][m]
    __shared__ float Ws[32][64];   // [k][n]
    const int tid = threadIdx.x;
    const int tx = tid & 15, ty = tid >> 4;
    const int m0 = blockIdx.y << 6;
    const int n0 = blockIdx.x << 6;

    float acc[4][4] = {};
    for (int k0 = 0; k0 < K; k0 += 32) {
#pragma unroll
        for (int l = 0; l < 2; l++) {
            int e = tid + l * 256;
            int row = e >> 3, c4 = (e & 7) << 2;
            float4 v = *(const float4*)(A + (size_t)(m0 + row) * K + k0 + c4);
            if (A2) {
                float4 v2 = *(const float4*)(A2 + (size_t)(m0 + row) * K + k0 + c4);
                v.x += v2.x; v.y += v2.y; v.z += v2.z; v.w += v2.w;
            }
            As[c4+0][row] = v.x; As[c4+1][row] = v.y;
            As[c4+2][row] = v.z; As[c4+3][row] = v.w;
            float4 w = *(const float4*)(W + (size_t)(n0 + row) * K + k0 + c4);
            Ws[c4+0][row] = w.x; Ws[c4+1][row] = w.y;
            Ws[c4+2][row] = w.z; Ws[c4+3][row] = w.w;
        }
        __syncthreads();
#pragma unroll
        for (int kk = 0; kk < 32; kk++) {
            float4 a = *(const float4*)&As[kk][ty << 2];
            float4 w = *(const float4*)&Ws[kk][tx << 2];
            float av[4] = {a.x, a.y, a.z, a.w};
            float wv[4] = {w.x, w.y, w.z, w.w};
#pragma unroll
            for (int i = 0; i < 4; i++)
#pragma unroll
                for (int j = 0; j < 4; j++)
                    acc[i][j] += av[i] * wv[j];
        }
        __syncthreads();
    }
#pragma unroll
    for (int i = 0; i < 4; i++) {
        float* cp = C + (size_t)(m0 + (ty << 2) + i) * N + n0 + (tx << 2);
#pragma unroll
        for (int j = 0; j < 4; j++)
            cp[j] = acc[i][j] + bscale * bias[n0 + (tx << 2) + j];
    }
}

// ---------------------------------------------------------------------------
// Flash causal softmax attention: y_ar = softmax(q k^T * 0.125, causal) @ v
// q,k from g_qk ([B,T,2D]); v = heads of x. Output merged [B,T,D].
// Block = one (b,h,q-tile of 64). 256 threads.
// ---------------------------------------------------------------------------
__global__ void __launch_bounds__(256) flash_ar_kernel(
    const float* __restrict__ qk, const float* __restrict__ x,
    float* __restrict__ yar)
{
    const int qt = blockIdx.x;
    const int b  = blockIdx.y >> 4;
    const int h  = blockIdx.y & 15;
    __shared__ float Qs[64][64];   // [d][r]  (q pre-scaled)
    __shared__ float Ks[64][64];   // [d][c], then reused as Pt[j][r]
    __shared__ float Vs[64][64];   // [j][c]
    const int tid = threadIdx.x;
    const int tx = tid & 15, ty = tid >> 4;
    const int q0 = qt << 6;

    const float* qbase = qk + (size_t)b * TT * (2*DD) + h * HD;
    const float* kbase = qbase + DD;
    const float* vbase = x + (size_t)b * TT * DD + h * HD;

#pragma unroll
    for (int l = 0; l < 4; l++) {
        int e = tid + l * 256;
        int r = e >> 4, d4 = (e & 15) << 2;
        float4 v = *(const float4*)(qbase + (size_t)(q0 + r) * (2*DD) + d4);
        Qs[d4+0][r] = v.x * 0.125f; Qs[d4+1][r] = v.y * 0.125f;
        Qs[d4+2][r] = v.z * 0.125f; Qs[d4+3][r] = v.w * 0.125f;
    }
    float mi[4], li[4], acc[4][4];
#pragma unroll
    for (int i = 0; i < 4; i++) {
        mi[i] = -INFINITY; li[i] = 0.f;
#pragma unroll
        for (int j = 0; j < 4; j++) acc[i][j] = 0.f;
    }
    __syncthreads();

    for (int kt = 0; kt <= qt; kt++) {
        const int k0 = kt << 6;
#pragma unroll
        for (int l = 0; l < 4; l++) {
            int e = tid + l * 256;
            int r = e >> 4, d4 = (e & 15) << 2;
            float4 kv = *(const float4*)(kbase + (size_t)(k0 + r) * (2*DD) + d4);
            Ks[d4+0][r] = kv.x; Ks[d4+1][r] = kv.y;
            Ks[d4+2][r] = kv.z; Ks[d4+3][r] = kv.w;
            float4 vv = *(const float4*)(vbase + (size_t)(k0 + r) * DD + d4);
            *(float4*)&Vs[r][d4] = vv;
        }
        __syncthreads();

        float s[4][4] = {};
#pragma unroll
        for (int d = 0; d < 64; d++) {
            float4 a  = *(const float4*)&Qs[d][ty << 2];
            float4 bb = *(const float4*)&Ks[d][tx << 2];
            float av[4] = {a.x, a.y, a.z, a.w};
            float bv[4] = {bb.x, bb.y, bb.z, bb.w};
#pragma unroll
            for (int i = 0; i < 4; i++)
#pragma unroll
                for (int j = 0; j < 4; j++)
                    s[i][j] += av[i] * bv[j];
        }
        if (kt == qt) {
#pragma unroll
            for (int i = 0; i < 4; i++)
#pragma unroll
                for (int j = 0; j < 4; j++)
                    if (k0 + (tx << 2) + j > q0 + (ty << 2) + i)
                        s[i][j] = -INFINITY;
        }
        // online softmax (row stats replicated across tx via 16-lane shuffles)
#pragma unroll
        for (int i = 0; i < 4; i++) {
            float rm = fmaxf(fmaxf(s[i][0], s[i][1]), fmaxf(s[i][2], s[i][3]));
            rm = fmaxf(rm, __shfl_xor_sync(0xffffffffu, rm, 1));
            rm = fmaxf(rm, __shfl_xor_sync(0xffffffffu, rm, 2));
            rm = fmaxf(rm, __shfl_xor_sync(0xffffffffu, rm, 4));
            rm = fmaxf(rm, __shfl_xor_sync(0xffffffffu, rm, 8));
            float mnew = fmaxf(mi[i], rm);
            float corr = __expf(mi[i] - mnew);
            float rs = 0.f;
#pragma unroll
            for (int j = 0; j < 4; j++) { s[i][j] = __expf(s[i][j] - mnew); rs += s[i][j]; }
            rs += __shfl_xor_sync(0xffffffffu, rs, 1);
            rs += __shfl_xor_sync(0xffffffffu, rs, 2);
            rs += __shfl_xor_sync(0xffffffffu, rs, 4);
            rs += __shfl_xor_sync(0xffffffffu, rs, 8);
            li[i] = li[i] * corr + rs;
            mi[i] = mnew;
#pragma unroll
            for (int j = 0; j < 4; j++) acc[i][j] *= corr;
        }
        __syncthreads();
#pragma unroll
        for (int i = 0; i < 4; i++)
#pragma unroll
            for (int j = 0; j < 4; j++)
                Ks[(tx << 2) + j][(ty << 2) + i] = s[i][j];   // Pt[j][r]
        __syncthreads();
#pragma unroll
        for (int jj = 0; jj < 64; jj++) {
            float4 p  = *(const float4*)&Ks[jj][ty << 2];
            float4 vv = *(const float4*)&Vs[jj][tx << 2];
            float pv[4] = {p.x, p.y, p.z, p.w};
            float vvv[4] = {vv.x, vv.y, vv.z, vv.w};
#pragma unroll
            for (int i = 0; i < 4; i++)
#pragma unroll
                for (int j = 0; j < 4; j++)
                    acc[i][j] += pv[i] * vvv[j];
        }
        __syncthreads();
    }
#pragma unroll
    for (int i = 0; i < 4; i++) {
        float inv = 1.f / li[i];
        float* op = yar + ((size_t)b * TT + q0 + (ty << 2) + i) * DD + h * HD + (tx << 2);
#pragma unroll
        for (int j = 0; j < 4; j++) op[j] = acc[i][j] * inv;
    }
}

// ---------------------------------------------------------------------------
// ARMA branch. Shifted space t in [0, T-2]:
//   qa_t = f(q[t+1]*0.125), f(u)=min(u, 0.02u)
//   ka_t = sigmoid(k2[t]*0.0025)
//   e_t  = v[t+1] - y_ar[t]
//   y_ma[t+1] = sum_{j<=t} (qa_t . ka_j) * e_j ;  y_ma[0] = 0
// Plain masked accumulation (no softmax).
// ---------------------------------------------------------------------------
__global__ void __launch_bounds__(256) flash_ma_kernel(
    const float* __restrict__ qk, const float* __restrict__ k2,
    const float* __restrict__ x,  const float* __restrict__ yar,
    float* __restrict__ yma)
{
    const int qt = blockIdx.x;
    const int b  = blockIdx.y >> 4;
    const int h  = blockIdx.y & 15;
    __shared__ float Qs[64][64];   // [d][r] qa
    __shared__ float Ks[64][64];   // [d][c] ka, then Pt[j][r]
    __shared__ float Vs[64][64];   // [j][c] e
    const int tid = threadIdx.x;
    const int tx = tid & 15, ty = tid >> 4;
    const int q0 = qt << 6;
    const int Tm = TT - 1;

    if (qt == 0 && tid < HD)   // y_ma row 0 = 0
        yma[(size_t)b * TT * DD + h * HD + tid] = 0.f;

    const float* qbase = qk + (size_t)b * TT * (2*DD) + h * HD;
    const float* kbase = k2 + (size_t)b * TT * DD + h * HD;
    const float* ebx   = x   + (size_t)b * TT * DD + h * HD;
    const float* eby   = yar + (size_t)b * TT * DD + h * HD;

#pragma unroll
    for (int l = 0; l < 4; l++) {
        int e = tid + l * 256;
        int r = e >> 4, d4 = (e & 15) << 2;
        int t = q0 + r;
        float u[4] = {0.f, 0.f, 0.f, 0.f};
        if (t < Tm) {
            float4 v = *(const float4*)(qbase + (size_t)(t + 1) * (2*DD) + d4);
            u[0] = v.x * 0.125f; u[1] = v.y * 0.125f;
            u[2] = v.z * 0.125f; u[3] = v.w * 0.125f;
        }
#pragma unroll
        for (int q = 0; q < 4; q++)
            Qs[d4 + q][r] = fminf(u[q], 0.02f * u[q]);
    }
    float acc[4][4];
#pragma unroll
    for (int i = 0; i < 4; i++)
#pragma unroll
        for (int j = 0; j < 4; j++) acc[i][j] = 0.f;
    __syncthreads();

    for (int kt = 0; kt <= qt; kt++) {
        const int k0 = kt << 6;
#pragma unroll
        for (int l = 0; l < 4; l++) {
            int e = tid + l * 256;
            int r = e >> 4, d4 = (e & 15) << 2;
            int t = k0 + r;
            if (t < Tm) {
                float4 kv = *(const float4*)(kbase + (size_t)t * DD + d4);
                Ks[d4+0][r] = 1.f / (1.f + __expf(-kv.x * 0.0025f));
                Ks[d4+1][r] = 1.f / (1.f + __expf(-kv.y * 0.0025f));
                Ks[d4+2][r] = 1.f / (1.f + __expf(-kv.z * 0.0025f));
                Ks[d4+3][r] = 1.f / (1.f + __expf(-kv.w * 0.0025f));
                float4 xv = *(const float4*)(ebx + (size_t)(t + 1) * DD + d4);
                float4 yv = *(const float4*)(eby + (size_t)t * DD + d4);
                float4 ev = make_float4(xv.x - yv.x, xv.y - yv.y, xv.z - yv.z, xv.w - yv.w);
                *(float4*)&Vs[r][d4] = ev;
            } else {
                Ks[d4+0][r] = 0.f; Ks[d4+1][r] = 0.f;
                Ks[d4+2][r] = 0.f; Ks[d4+3][r] = 0.f;
                *(float4*)&Vs[r][d4] = make_float4(0.f, 0.f, 0.f, 0.f);
            }
        }
        __syncthreads();

        float s[4][4] = {};
#pragma unroll
        for (int d = 0; d < 64; d++) {
            float4 a  = *(const float4*)&Qs[d][ty << 2];
            float4 bb = *(const float4*)&Ks[d][tx << 2];
            float av[4] = {a.x, a.y, a.z, a.w};
            float bv[4] = {bb.x, bb.y, bb.z, bb.w};
#pragma unroll
            for (int i = 0; i < 4; i++)
#pragma unroll
                for (int j = 0; j < 4; j++)
                    s[i][j] += av[i] * bv[j];
        }
        if (kt == qt) {
#pragma unroll
            for (int i = 0; i < 4; i++)
#pragma unroll
                for (int j = 0; j < 4; j++)
                    if (k0 + (tx << 2) + j > q0 + (ty << 2) + i)
                        s[i][j] = 0.f;
        }
        __syncthreads();
#pragma unroll
        for (int i = 0; i < 4; i++)
#pragma unroll
            for (int j = 0; j < 4; j++)
                Ks[(tx << 2) + j][(ty << 2) + i] = s[i][j];
        __syncthreads();
#pragma unroll
        for (int jj = 0; jj < 64; jj++) {
            float4 p  = *(const float4*)&Ks[jj][ty << 2];
            float4 vv = *(const float4*)&Vs[jj][tx << 2];
            float pv[4] = {p.x, p.y, p.z, p.w};
            float vvv[4] = {vv.x, vv.y, vv.z, vv.w};
#pragma unroll
            for (int i = 0; i < 4; i++)
#pragma unroll
                for (int j = 0; j < 4; j++)
                    acc[i][j] += pv[i] * vvv[j];
        }
        __syncthreads();
    }
#pragma unroll
    for (int i = 0; i < 4; i++) {
        int t = q0 + (ty << 2) + i;
        if (t < Tm) {
            float* op = yma + ((size_t)b * TT + t + 1) * DD + h * HD + (tx << 2);
#pragma unroll
            for (int j = 0; j < 4; j++) op[j] = acc[i][j];
        }
    }
}

// ---------------------------------------------------------------------------
extern "C" void kernel_launch(void* const* d_in, const int* in_sizes, int n_in,
                              void* d_out, int out_size)
{
    (void)in_sizes; (void)n_in; (void)out_size;
    const float* x      = (const float*)d_in[0];
    const float* w_attn = (const float*)d_in[1];
    const float* b_attn = (const float*)d_in[2];
    const float* w_k2   = (const float*)d_in[3];
    const float* b_k2   = (const float*)d_in[4];
    const float* w_proj = (const float*)d_in[5];
    const float* b_proj = (const float*)d_in[6];
    float* out = (float*)d_out;

    float *qkp, *k2p, *yarp, *ymap;
    cudaGetSymbolAddress((void**)&qkp,  g_qk);
    cudaGetSymbolAddress((void**)&k2p,  g_k2);
    cudaGetSymbolAddress((void**)&yarp, g_yar);
    cudaGetSymbolAddress((void**)&ymap, g_yma);

    dim3 blk(256);
    // 1) qk = x @ w_attn^T + b_attn   [4096, 2048]
    gemm_atb_kernel<<<dim3((2*DD)/64, MM/64), blk>>>(x, nullptr, w_attn, b_attn, 1.f, qkp, 2*DD, DD);
    // 2) k2 = x @ w_k2^T + b_k2       [4096, 1024]
    gemm_atb_kernel<<<dim3(DD/64, MM/64), blk>>>(x, nullptr, w_k2, b_k2, 1.f, k2p, DD, DD);
    // 3) y_ar (causal softmax attention)
    flash_ar_kernel<<<dim3(TT/64, BB*HH), blk>>>(qkp, x, yarp);
    // 4) y_ma (ARMA masked attention)
    flash_ma_kernel<<<dim3(TT/64, BB*HH), blk>>>(qkp, k2p, x, yarp, ymap);
    // 5) out = (y_ar + y_ma) @ w_proj^T + 2*b_proj
    gemm_atb_kernel<<<dim3(DD/64, MM/64), blk>>>(yarp, ymap, w_proj, b_proj, 2.f, out, DD, DD);
}